// round 4
// baseline (speedup 1.0000x reference)
#include <cuda_runtime.h>
#include <math.h>

#define MAXB 4096
__device__ float    g_seg_bce[MAXB];   // zero-init at module load; last block re-zeroes
__device__ float    g_seg_cnt[MAXB];
__device__ unsigned g_ticket;          // zero-init; last block resets

__device__ __forceinline__ float bce_fast(float p, float t) {
    float lp = fmaxf(__logf(p),        -100.0f);   // __logf(0) = -inf -> -100
    float lq = fmaxf(__logf(1.0f - p), -100.0f);
    return -(t * lp + (1.0f - t) * lq);
}

// Process one coalesced float4 chunk. Must be entered by ALL lanes of the warp
// (branch condition warp-uniform). Lanes with !valid contribute nothing.
__device__ __forceinline__ void handle_chunk(bool valid, unsigned act,
                                             float4 p4, float4 t4,
                                             int4 s4, int4 k4,
                                             unsigned lane) {
    const unsigned FULL = 0xffffffffu;
    float b = 0.0f, m = 0.0f;
    float b0=0,b1=0,b2=0,b3=0, m0=0,m1=0,m2=0,m3=0;
    if (valid) {
        m0 = (float)k4.x; m1 = (float)k4.y; m2 = (float)k4.z; m3 = (float)k4.w;
        b0 = bce_fast(p4.x * m0, t4.x);
        b1 = bce_fast(p4.y * m1, t4.y);
        b2 = bce_fast(p4.z * m2, t4.z);
        b3 = bce_fast(p4.w * m3, t4.w);
        b = (b0 + b1) + (b2 + b3);
        m = (m0 + m1) + (m2 + m3);
    }
    int wlo = __shfl_sync(FULL, s4.x, 0);
    int whi = __shfl_sync(FULL, s4.w, 31);

    if (act == FULL && wlo == whi) {
        // fast path: 128 contiguous nodes, one segment
        #pragma unroll
        for (int o = 16; o; o >>= 1) {
            b += __shfl_down_sync(FULL, b, o);
            m += __shfl_down_sync(FULL, m, o);
        }
        if (lane == 0) {
            atomicAdd(&g_seg_bce[wlo], b);
            atomicAdd(&g_seg_cnt[wlo], m);
        }
    } else if (valid) {
        if (s4.x == s4.w) {
            atomicAdd(&g_seg_bce[s4.x], b);
            atomicAdd(&g_seg_cnt[s4.x], m);
        } else {
            atomicAdd(&g_seg_bce[s4.x], b0); atomicAdd(&g_seg_cnt[s4.x], m0);
            atomicAdd(&g_seg_bce[s4.y], b1); atomicAdd(&g_seg_cnt[s4.y], m1);
            atomicAdd(&g_seg_bce[s4.z], b2); atomicAdd(&g_seg_cnt[s4.z], m2);
            atomicAdd(&g_seg_bce[s4.w], b3); atomicAdd(&g_seg_cnt[s4.w], m3);
        }
    }
}

__global__ void __launch_bounds__(256) fused_kernel(
        const float* __restrict__ pred,
        const float* __restrict__ tgt,
        const int*   __restrict__ batch,
        const int*   __restrict__ mask,
        const float* __restrict__ sat_p,
        const float* __restrict__ sat_t,
        float*       __restrict__ out,
        int n4, int N, int B, float l1)
{
    const unsigned FULL = 0xffffffffu;
    const float4* pred4  = (const float4*)pred;
    const float4* tgt4   = (const float4*)tgt;
    const int4*   batch4 = (const int4*)batch;
    const int4*   mask4  = (const int4*)mask;

    // ---- main phase: two BLOCK-STRIDED coalesced chunks per block ----
    int base = blockIdx.x * (int)(blockDim.x * 2);
    int gA = base + threadIdx.x;
    int gB = gA + blockDim.x;
    unsigned lane = threadIdx.x & 31;

    bool vA = (gA < n4), vB = (gB < n4);
    unsigned actA = __ballot_sync(FULL, vA);
    unsigned actB = __ballot_sync(FULL, vB);

    // issue all loads up front (MLP = 8 LDG.128 per thread)
    float4 pA = {}, tA = {}; int4 sA = {}, kA = {};
    float4 pB = {}, tB = {}; int4 sB = {}, kB = {};
    if (vA) { pA = pred4[gA]; tA = tgt4[gA]; sA = batch4[gA]; kA = mask4[gA]; }
    if (vB) { pB = pred4[gB]; tB = tgt4[gB]; sB = batch4[gB]; kB = mask4[gB]; }

    if (actA) handle_chunk(vA, actA, pA, tA, sA, kA, lane);
    if (actB) handle_chunk(vB, actB, pB, tB, sB, kB, lane);

    // scalar tail (N % 4), handled by block 0
    int tail = N - (n4 << 2);
    if (blockIdx.x == 0 && (int)threadIdx.x < tail) {
        int i = (n4 << 2) + threadIdx.x;
        float mm = (float)mask[i];
        atomicAdd(&g_seg_bce[batch[i]], bce_fast(pred[i] * mm, tgt[i]));
        atomicAdd(&g_seg_cnt[batch[i]], mm);
    }

    // ---- last-block epilogue ----
    __shared__ int sh_last;
    __shared__ float sh[32];
    __syncthreads();
    __threadfence();
    if (threadIdx.x == 0) {
        unsigned t = atomicAdd(&g_ticket, 1u);
        sh_last = (t == gridDim.x - 1) ? 1 : 0;
    }
    __syncthreads();
    if (!sh_last) return;

    float acc = 0.0f, sat = 0.0f;
    for (int i = threadIdx.x; i < B; i += blockDim.x) {
        float c  = __ldcg(&g_seg_cnt[i]);
        float sb = __ldcg(&g_seg_bce[i]);
        acc += (c > 0.0f) ? (sb / fmaxf(c, 1.0f)) : 0.0f;
        sat += bce_fast(sat_p[i], sat_t[i]);
        g_seg_cnt[i] = 0.0f;                 // re-zero for next graph replay
        g_seg_bce[i] = 0.0f;
    }
    float v = acc + sat * (l1 / (float)B);
    #pragma unroll
    for (int o = 16; o; o >>= 1) v += __shfl_down_sync(FULL, v, o);
    int wid = threadIdx.x >> 5;
    if (lane == 0) sh[wid] = v;
    __syncthreads();
    if (wid == 0) {
        int nw = (blockDim.x + 31) >> 5;
        v = (lane < (unsigned)nw) ? sh[lane] : 0.0f;
        #pragma unroll
        for (int o = 16; o; o >>= 1) v += __shfl_down_sync(FULL, v, o);
        if (lane == 0) {
            out[0] = v;
            atomicExch(&g_ticket, 0u);       // reset for next replay
        }
    }
}

extern "C" void kernel_launch(void* const* d_in, const int* in_sizes, int n_in,
                              void* d_out, int out_size) {
    const float* y_mus_pred = (const float*)d_in[0];
    const float* y_mus      = (const float*)d_in[1];
    const float* y_sat_pred = (const float*)d_in[2];
    const float* y_sat      = (const float*)d_in[3];
    const int*   batch      = (const int*)  d_in[4];
    const int*   mask       = (const int*)  d_in[5];
    int N = in_sizes[0];
    int B = in_sizes[2];
    float L1 = 1.0f / 50.0f;

    int n4 = N >> 2;
    int groups_per_block = 256 * 2;
    int blocks = (n4 + groups_per_block - 1) / groups_per_block;
    if (blocks < 1) blocks = 1;

    fused_kernel<<<blocks, 256>>>(y_mus_pred, y_mus, batch, mask,
                                  y_sat_pred, y_sat, (float*)d_out,
                                  n4, N, B, L1);
}

// round 5
// speedup vs baseline: 1.7869x; 1.7869x over previous
#include <cuda_runtime.h>
#include <math.h>

#define MAXB 4096
__device__ float    g_seg_bce[MAXB];   // zero-init at module load; finalize re-zeroes
__device__ float    g_seg_cnt[MAXB];
__device__ float    g_total;           // zero-init; finalize resets
__device__ unsigned g_ticket;          // zero-init; finalize resets

__device__ __forceinline__ float bce_fast(float p, float t) {
    float lp = fmaxf(__logf(p),        -100.0f);   // __logf(0) = -inf -> -100
    float lq = fmaxf(__logf(1.0f - p), -100.0f);
    return -(t * lp + (1.0f - t) * lq);
}

// ---- node kernel: exact round-2 structure (MLP_p1 = 4, coalesced LDG.128) ----
__global__ void __launch_bounds__(256) node_kernel(
        const float4* __restrict__ pred4,
        const float4* __restrict__ tgt4,
        const int4*   __restrict__ batch4,
        const int4*   __restrict__ mask4,
        int n4)
{
    const unsigned FULL = 0xffffffffu;
    int i = blockIdx.x * blockDim.x + threadIdx.x;
    if (i >= n4) return;

    float4 p4 = __ldcs(&pred4[i]);     // single-use stream: evict-first
    float4 t4 = __ldcs(&tgt4[i]);
    int4   s4 = __ldcs(&batch4[i]);
    int4   k4 = __ldcs(&mask4[i]);

    float m0 = (float)k4.x, m1 = (float)k4.y, m2 = (float)k4.z, m3 = (float)k4.w;
    float b0 = bce_fast(p4.x * m0, t4.x);
    float b1 = bce_fast(p4.y * m1, t4.y);
    float b2 = bce_fast(p4.z * m2, t4.z);
    float b3 = bce_fast(p4.w * m3, t4.w);

    unsigned act = __ballot_sync(FULL, 1);
    int wlo = __shfl_sync(FULL, s4.x, 0);
    int whi = __shfl_sync(FULL, s4.w, 31);

    if (act == FULL && wlo == whi) {
        // fast path: 128 contiguous nodes in one segment (batch sorted)
        float b = (b0 + b1) + (b2 + b3);
        float m = (m0 + m1) + (m2 + m3);
        #pragma unroll
        for (int o = 16; o; o >>= 1) {
            b += __shfl_down_sync(FULL, b, o);
            m += __shfl_down_sync(FULL, m, o);
        }
        if ((threadIdx.x & 31) == 0) {
            atomicAdd(&g_seg_bce[wlo], b);
            atomicAdd(&g_seg_cnt[wlo], m);
        }
        return;
    }
    if (s4.x == s4.w) {
        atomicAdd(&g_seg_bce[s4.x], (b0 + b1) + (b2 + b3));
        atomicAdd(&g_seg_cnt[s4.x], (m0 + m1) + (m2 + m3));
    } else {
        atomicAdd(&g_seg_bce[s4.x], b0); atomicAdd(&g_seg_cnt[s4.x], m0);
        atomicAdd(&g_seg_bce[s4.y], b1); atomicAdd(&g_seg_cnt[s4.y], m1);
        atomicAdd(&g_seg_bce[s4.z], b2); atomicAdd(&g_seg_cnt[s4.z], m2);
        atomicAdd(&g_seg_bce[s4.w], b3); atomicAdd(&g_seg_cnt[s4.w], m3);
    }
}

// scalar tail (N % 4)
__global__ void tail_kernel(const float* __restrict__ pred,
                            const float* __restrict__ tgt,
                            const int*   __restrict__ batch,
                            const int*   __restrict__ mask,
                            int start, int n)
{
    int i = start + blockIdx.x * blockDim.x + threadIdx.x;
    if (i >= n) return;
    float m = (float)mask[i];
    atomicAdd(&g_seg_bce[batch[i]], bce_fast(pred[i] * m, tgt[i]));
    atomicAdd(&g_seg_cnt[batch[i]], m);
}

// ---- parallel finalize: NBLK blocks, partial sums + cheap ticket ----
#define FIN_BLOCKS 16
__global__ void __launch_bounds__(256) finalize_kernel(
        const float* __restrict__ sat_p,
        const float* __restrict__ sat_t,
        float* __restrict__ out,
        int B, float l1)
{
    const unsigned FULL = 0xffffffffu;
    __shared__ float sh[8];
    __shared__ int sh_last;

    float acc = 0.0f;
    for (int i = blockIdx.x * blockDim.x + threadIdx.x; i < B;
         i += gridDim.x * blockDim.x) {
        float c  = g_seg_cnt[i];
        float sb = g_seg_bce[i];
        acc += (c > 0.0f) ? (sb / fmaxf(c, 1.0f)) : 0.0f;
        acc += bce_fast(sat_p[i], sat_t[i]) * (l1 / (float)B);
        g_seg_cnt[i] = 0.0f;            // re-zero for next graph replay
        g_seg_bce[i] = 0.0f;
    }
    // block reduce
    #pragma unroll
    for (int o = 16; o; o >>= 1) acc += __shfl_down_sync(FULL, acc, o);
    int lane = threadIdx.x & 31, wid = threadIdx.x >> 5;
    if (lane == 0) sh[wid] = acc;
    __syncthreads();
    if (wid == 0) {
        acc = (lane < (blockDim.x >> 5)) ? sh[lane] : 0.0f;
        #pragma unroll
        for (int o = 16; o; o >>= 1) acc += __shfl_down_sync(FULL, acc, o);
        if (lane == 0) atomicAdd(&g_total, acc);
    }
    // ticket: only gridDim.x fences total — cheap
    __syncthreads();
    __threadfence();
    if (threadIdx.x == 0) {
        unsigned t = atomicAdd(&g_ticket, 1u);
        sh_last = (t == gridDim.x - 1) ? 1 : 0;
    }
    __syncthreads();
    if (sh_last && threadIdx.x == 0) {
        out[0] = __ldcg(&g_total);
        g_total = 0.0f;                 // reset for next replay
        atomicExch(&g_ticket, 0u);
    }
}

extern "C" void kernel_launch(void* const* d_in, const int* in_sizes, int n_in,
                              void* d_out, int out_size) {
    const float* y_mus_pred = (const float*)d_in[0];
    const float* y_mus      = (const float*)d_in[1];
    const float* y_sat_pred = (const float*)d_in[2];
    const float* y_sat      = (const float*)d_in[3];
    const int*   batch      = (const int*)  d_in[4];
    const int*   mask       = (const int*)  d_in[5];
    int N = in_sizes[0];
    int B = in_sizes[2];
    float L1 = 1.0f / 50.0f;

    int n4 = N >> 2;
    if (n4 > 0) {
        int blocks = (n4 + 255) / 256;
        node_kernel<<<blocks, 256>>>((const float4*)y_mus_pred,
                                     (const float4*)y_mus,
                                     (const int4*)batch,
                                     (const int4*)mask, n4);
    }
    int tail_start = n4 << 2;
    if (tail_start < N) {
        tail_kernel<<<1, 256>>>(y_mus_pred, y_mus, batch, mask, tail_start, N);
    }
    finalize_kernel<<<FIN_BLOCKS, 256>>>(y_sat_pred, y_sat, (float*)d_out, B, L1);
}